// round 1
// baseline (speedup 1.0000x reference)
#include <cuda_runtime.h>
#include <cstdint>

typedef unsigned int u32;

// ============================================================================
// JAX threefry2x32 block (20 rounds), exact.
// ============================================================================
__device__ __forceinline__ void tf2x32(u32 k0, u32 k1, u32 x0, u32 x1, u32 &o0, u32 &o1)
{
    u32 k2 = k0 ^ k1 ^ 0x1BD11BDAu;
    x0 += k0; x1 += k1;
#define TF_R(r) { x0 += x1; x1 = __funnelshift_l(x1, x1, (r)); x1 ^= x0; }
    TF_R(13) TF_R(15) TF_R(26) TF_R(6)
    x0 += k1; x1 += k2 + 1u;
    TF_R(17) TF_R(29) TF_R(16) TF_R(24)
    x0 += k2; x1 += k0 + 2u;
    TF_R(13) TF_R(15) TF_R(26) TF_R(6)
    x0 += k0; x1 += k1 + 3u;
    TF_R(17) TF_R(29) TF_R(16) TF_R(24)
    x0 += k1; x1 += k2 + 4u;
    TF_R(13) TF_R(15) TF_R(26) TF_R(6)
    x0 += k2; x1 += k0 + 5u;
#undef TF_R
    o0 = x0; o1 = x1;
}

// ============================================================================
// PARTITIONABLE-mode primitives (jax_threefry_partitionable=True, JAX >= 0.5):
//   split(key, n)[i]      = TF(key, hi(i), lo(i))       (both words = new key)
//   random_bits32 elem i  = x0 ^ x1 of TF(key, hi(i), lo(i))
// (If this guess is wrong -> flip to original iota/half-split scheme in R1.)
// ============================================================================

__device__ __forceinline__ float bits_to_f01(u32 b)
{
    // (bits >> 9) | 0x3f800000 bitcast -> [1,2), minus 1 -> [0,1)
    return __uint_as_float((b >> 9) | 0x3f800000u) - 1.0f;
}

// XLA ErfInv (f32, Giles polynomial) — exact algorithm XLA lowers to.
__device__ __forceinline__ float xla_erfinv(float x)
{
    float w = -log1pf(-__fmul_rn(x, x));
    float p;
    if (w < 5.0f) {
        w = __fsub_rn(w, 2.5f);
        p = 2.81022636e-08f;
        p = __fadd_rn(3.43273939e-07f,  __fmul_rn(p, w));
        p = __fadd_rn(-3.5233877e-06f,  __fmul_rn(p, w));
        p = __fadd_rn(-4.39150654e-06f, __fmul_rn(p, w));
        p = __fadd_rn(0.00021858087f,   __fmul_rn(p, w));
        p = __fadd_rn(-0.00125372503f,  __fmul_rn(p, w));
        p = __fadd_rn(-0.00417768164f,  __fmul_rn(p, w));
        p = __fadd_rn(0.246640727f,     __fmul_rn(p, w));
        p = __fadd_rn(1.50140941f,      __fmul_rn(p, w));
    } else {
        w = __fsub_rn(sqrtf(w), 3.0f);
        p = -0.000200214257f;
        p = __fadd_rn(0.000100950558f,  __fmul_rn(p, w));
        p = __fadd_rn(0.00134934322f,   __fmul_rn(p, w));
        p = __fadd_rn(-0.00367342844f,  __fmul_rn(p, w));
        p = __fadd_rn(0.00573950773f,   __fmul_rn(p, w));
        p = __fadd_rn(-0.0076224613f,   __fmul_rn(p, w));
        p = __fadd_rn(0.00943887047f,   __fmul_rn(p, w));
        p = __fadd_rn(1.00167406f,      __fmul_rn(p, w));
        p = __fadd_rn(2.83297682f,      __fmul_rn(p, w));
    }
    return __fmul_rn(p, x);
}

// jax.random.normal(key, ()) — scalar, partitionable bits
__device__ __forceinline__ float normal_scalar_pt(u32 k0, u32 k1)
{
    u32 o0, o1; tf2x32(k0, k1, 0u, 0u, o0, o1);
    float f = bits_to_f01(o0 ^ o1);
    const float lo = -0.99999994f;          // nextafter(-1,0) in f32
    float u = __fadd_rn(__fmul_rn(f, 2.0f), lo);  // (hi-lo) rounds to exactly 2.0f
    u = fmaxf(lo, u);
    return __fmul_rn(1.41421356237f, xla_erfinv(u)); // sqrt(2) f32
}

// jax.random.uniform(key, (), 0, 1) — scalar
__device__ __forceinline__ float uniform01_scalar_pt(u32 k0, u32 k1)
{
    u32 o0, o1; tf2x32(k0, k1, 0u, 0u, o0, o1);
    return bits_to_f01(o0 ^ o1);   // *(1-0)+0 then max(0,.) == identity
}

// _gamma_one(key, alpha) for alpha >= 1 (boost branch dead), non-log-space.
// Exact key-splitting structure of jax/_src/random.py.
__device__ float gamma_pt(u32 k0, u32 k1, float dd, float cc)
{
    // key, subkey = split(key)  (subkey only feeds the dead boost branch)
    { u32 n0, n1; tf2x32(k0, k1, 0u, 0u, n0, n1); k0 = n0; k1 = n1; }

    float X = 0.0f, V = 1.0f, U = 2.0f;
    for (;;) {
        // cond: (U >= 1 - 0.0331*X*X) && (log U >= 0.5*X + d*(1 - V + log V))
        bool c1 = (U >= __fsub_rn(1.0f, __fmul_rn(0.0331f, __fmul_rn(X, X))));
        if (c1) {
            float rhs = __fadd_rn(__fmul_rn(X, 0.5f),
                        __fmul_rn(dd, __fadd_rn(__fsub_rn(1.0f, V), logf(V))));
            if (!(logf(U) >= rhs)) break;
        } else break;

        // key, x_key, U_key = split(key, 3)
        u32 a0, a1, b0, b1, c0, c1_;
        tf2x32(k0, k1, 0u, 0u, a0, a1);
        tf2x32(k0, k1, 0u, 1u, b0, b1);
        tf2x32(k0, k1, 0u, 2u, c0, c1_);
        k0 = a0; k1 = a1;
        u32 xk0 = b0, xk1 = b1;

        float x, v;
        do { // while v <= 0: x_key, sk = split(x_key); x = normal(sk)
            u32 s0, s1, t0, t1;
            tf2x32(xk0, xk1, 0u, 0u, s0, s1);
            tf2x32(xk0, xk1, 0u, 1u, t0, t1);
            xk0 = s0; xk1 = s1;
            x = normal_scalar_pt(t0, t1);
            v = __fadd_rn(1.0f, __fmul_rn(x, cc));
        } while (v <= 0.0f);

        X = __fmul_rn(x, x);
        V = __fmul_rn(__fmul_rn(v, v), v);
        U = uniform01_scalar_pt(c0, c1_);
    }
    return __fmul_rn(dd, V);
}

// ============================================================================
// KL scalar (kernel 1)
// ============================================================================
__device__ float g_klsum;

__device__ __forceinline__ float digammaf_(float x)
{
    float acc = 0.0f;
    while (x < 8.0f) { acc -= __fdiv_rn(1.0f, x); x += 1.0f; }
    float ix  = __fdiv_rn(1.0f, x);
    float ix2 = ix * ix;
    float s = logf(x) - 0.5f * ix
            - ix2 * (0.0833333333f - ix2 * (0.00833333333f - ix2 * 0.00396825397f));
    return s + acc;
}

__global__ void kl_kernel(const float* __restrict__ locs, const float* __restrict__ scales,
                          const float* __restrict__ alpha, const float* __restrict__ beta,
                          const float* __restrict__ counts)
{
    __shared__ float red[256];
    float acc = 0.0f;
    for (int i = threadIdx.x; i < 4096; i += 256) {
        float lc = locs[i], sc = scales[i], al = alpha[i], be = beta[i];
        // KL(N(loc,scale) || N(0,1))
        acc += -logf(sc) + 0.5f * (sc * sc + lc * lc) - 0.5f;
        // KL(Gamma(al,be) || Gamma(5,5))
        acc += (al - 5.0f) * digammaf_(al) - lgammaf(al) + lgammaf(5.0f)
             + 5.0f * (logf(be) - logf(5.0f)) + al * (5.0f - be) / be;
    }
    red[threadIdx.x] = acc;
    __syncthreads();
    for (int s = 128; s > 0; s >>= 1) {
        if (threadIdx.x < (unsigned)s) red[threadIdx.x] += red[threadIdx.x + s];
        __syncthreads();
    }
    if (threadIdx.x == 0) {
        float c0 = 0.0f;
        for (int k = 0; k < 64; ++k) c0 += counts[k];
        float a0 = 2.0f * 64.0f;
        float td = lgammaf(c0) - lgammaf(a0);
        float dgc0 = digammaf_(c0);
        for (int k = 0; k < 64; ++k) {
            float ck = counts[k];
            td += lgammaf(2.0f) - lgammaf(ck);
            td += (ck - 2.0f) * (digammaf_(ck) - dgc0);
        }
        g_klsum = red[0] + td;
    }
}

// ============================================================================
// Main per-sample loss kernel: 1 block per n, 256 threads (4 per component k)
// ============================================================================
__global__ __launch_bounds__(256) void loss_kernel(
    const float* __restrict__ x,     const float* __restrict__ locs,
    const float* __restrict__ scales,const float* __restrict__ alphas,
    const float* __restrict__ betas, const float* __restrict__ counts,
    float* __restrict__ out)
{
    const int n = blockIdx.x;
    const int t = threadIdx.x;
    const int k = t >> 2;
    const int q = t & 3;

    __shared__ float s_x[64];
    __shared__ float s_comp[64];
    __shared__ float s_gd[64];

    if (t < 64) s_x[t] = x[n * 64 + t];

    // root key = key(42) -> (0,42); ke,kg,kd = split(root, 3) [foldlike]
    u32 ke0, ke1, kg0, kg1, kd0, kd1;
    tf2x32(0u, 42u, 0u, 0u, ke0, ke1);
    tf2x32(0u, 42u, 0u, 1u, kg0, kg1);
    tf2x32(0u, 42u, 0u, 2u, kd0, kd1);
    __syncthreads();

    float zsum = 0.0f, lsum = 0.0f;
    const int kd_base = k * 64 + q * 16;
#pragma unroll 1
    for (int j = 0; j < 16; ++j) {
        int kdidx = kd_base + j;
        int d = kdidx & 63;
        u32 i = (u32)n * 4096u + (u32)kdidx;

        // eps[n,k,d]: normal over (N,K,D) from ke, partitionable bits
        u32 e0, e1; tf2x32(ke0, ke1, 0u, i, e0, e1);
        float f = bits_to_f01(e0 ^ e1);
        const float lo = -0.99999994f;
        float u = fmaxf(lo, __fadd_rn(__fmul_rn(f, 2.0f), lo));
        float eps = __fmul_rn(1.41421356237f, xla_erfinv(u));

        float lc = __ldg(locs + kdidx), sc = __ldg(scales + kdidx);
        float mu = __fadd_rn(lc, __fmul_rn(sc, eps));

        // g[n,k,d] ~ Gamma(alpha[k,d]); element key = TF(kg, 0, i)
        float al = __ldg(alphas + kdidx);
        float dd = __fsub_rn(al, 0.33333334f);
        float cc = __fdiv_rn(0.33333334f, sqrtf(dd));
        u32 gk0, gk1; tf2x32(kg0, kg1, 0u, i, gk0, gk1);
        float g = gamma_pt(gk0, gk1, dd, cc);

        float be = __ldg(betas + kdidx);
        float r  = __fdiv_rn(g, be);           // sigma^-2
        float diff = __fsub_rn(s_x[d], mu);
        zsum += __fmul_rn(__fmul_rn(diff, diff), r);
        lsum += logf(r);                       // sum log sigma = -0.5 * lsum
    }

    // reduce the 4 lanes of component k (consecutive lanes)
    zsum += __shfl_xor_sync(0xffffffffu, zsum, 1);
    zsum += __shfl_xor_sync(0xffffffffu, zsum, 2);
    lsum += __shfl_xor_sync(0xffffffffu, lsum, 1);
    lsum += __shfl_xor_sync(0xffffffffu, lsum, 2);

    if (q == 0) {
        float sumlogsig = -0.5f * lsum;
        float comp = -0.5f * zsum - sumlogsig - 58.81206612509905f; // 0.5*D*log(2pi)
        // Dirichlet gamma gd[n,k], alpha = counts[k]
        u32 jidx = (u32)n * 64u + (u32)k;
        u32 dk0, dk1; tf2x32(kd0, kd1, 0u, jidx, dk0, dk1);
        float ck = __ldg(counts + k);
        float dd = __fsub_rn(ck, 0.33333334f);
        float cc = __fdiv_rn(0.33333334f, sqrtf(dd));
        float gd = gamma_pt(dk0, dk1, dd, cc);
        s_comp[k] = comp;
        s_gd[k]   = gd;
    }
    __syncthreads();

    if (t < 32) {
        float g0 = s_gd[t], g1 = s_gd[t + 32];
        float S = g0 + g1;
        for (int m = 16; m; m >>= 1) S += __shfl_xor_sync(0xffffffffu, S, m);
        float t0 = logf(__fdiv_rn(g0, S)) + s_comp[t];
        float t1 = logf(__fdiv_rn(g1, S)) + s_comp[t + 32];
        float mx = fmaxf(t0, t1);
        for (int m = 16; m; m >>= 1) mx = fmaxf(mx, __shfl_xor_sync(0xffffffffu, mx, m));
        float es = expf(t0 - mx) + expf(t1 - mx);
        for (int m = 16; m; m >>= 1) es += __shfl_xor_sync(0xffffffffu, es, m);
        if (t == 0) {
            float log_lik = mx + logf(es);
            out[n] = g_klsum / 8192.0f - log_lik;
        }
    }
}

// ============================================================================
extern "C" void kernel_launch(void* const* d_in, const int* in_sizes, int n_in,
                              void* d_out, int out_size)
{
    (void)in_sizes; (void)n_in; (void)out_size;
    const float* x      = (const float*)d_in[0];
    const float* locs   = (const float*)d_in[1];
    const float* scales = (const float*)d_in[2];
    const float* alpha  = (const float*)d_in[3];
    const float* beta   = (const float*)d_in[4];
    const float* counts = (const float*)d_in[5];
    float* out = (float*)d_out;

    kl_kernel<<<1, 256>>>(locs, scales, alpha, beta, counts);
    loss_kernel<<<8192, 256>>>(x, locs, scales, alpha, beta, counts, out);
}